// round 2
// baseline (speedup 1.0000x reference)
#include <cuda_runtime.h>
#include <math.h>

// HashGrid: 10-level Instant-NGP hash encoding, 2M points, FEAT_DIM=3.
// All codebooks (5255 entries total, padded to float4 = 84,080 B) live in
// dynamic shared memory; persistent grid-stride kernel, one point per thread
// per iteration, 80 random LDS.128 gathers per point.

#define NLOD 10

struct Params { const float* cb[NLOD]; };

// sizes = min(lod^2, 1024) for lods {7,8,11,14,18,23,30,38,50,64/65}
__host__ __device__ constexpr int H_SIZES(int l) {
    constexpr int s[NLOD] = {49, 64, 121, 196, 324, 529, 900, 1024, 1024, 1024};
    return s[l];
}
__host__ __device__ constexpr int H_OFFS(int l) {
    constexpr int o[NLOD] = {0, 49, 113, 234, 430, 754, 1283, 2183, 3207, 4231};
    return o[l];
}
constexpr int H_TOTAL = 5255;
constexpr int SMEM_BYTES = H_TOTAL * 16;  // 84080 bytes
constexpr int THREADS = 512;

template <int LAST_RES>
__global__ __launch_bounds__(THREADS, 2)
void hashgrid_kernel(const float* __restrict__ pts, Params prm,
                     float* __restrict__ out, int n)
{
    extern __shared__ float4 scb[];

    // ---- Stage all codebooks into shared memory, padded to 16B entries ----
    #pragma unroll
    for (int l = 0; l < NLOD; l++) {
        const float* __restrict__ src = prm.cb[l];
        const int sz = H_SIZES(l);
        const int off = H_OFFS(l);
        for (int i = threadIdx.x; i < sz; i += THREADS) {
            scb[off + i] = make_float4(src[3 * i], src[3 * i + 1], src[3 * i + 2], 0.0f);
        }
    }
    __syncthreads();

    const int stride = gridDim.x * THREADS;
    for (int i = blockIdx.x * THREADS + threadIdx.x; i < n; i += stride) {
        const float px = pts[3 * i + 0];
        const float py = pts[3 * i + 1];
        const float pz = pts[3 * i + 2];
        float a0 = 0.0f, a1 = 0.0f, a2 = 0.0f;

        #pragma unroll
        for (int l = 0; l < NLOD; l++) {
            constexpr int RESA[NLOD] = {7, 8, 11, 14, 18, 23, 30, 38, 50, LAST_RES};
            const int R = RESA[l];
            const unsigned S = (unsigned)H_SIZES(l);   // compile-time -> magic-number mod
            const int O = H_OFFS(l);
            const float scale = (float)(R - 1);

            const float xs = px * scale, ys = py * scale, zs = pz * scale;
            int x0 = (int)xs; x0 = x0 > R - 2 ? R - 2 : x0;  // xs >= 0 so trunc == floor
            int y0 = (int)ys; y0 = y0 > R - 2 ? R - 2 : y0;
            int z0 = (int)zs; z0 = z0 > R - 2 ? R - 2 : z0;
            const float wx = xs - (float)x0, wy = ys - (float)y0, wz = zs - (float)z0;
            const float ux = 1.0f - wx, uy = 1.0f - wy, uz = 1.0f - wz;

            // Instant-NGP primes: {1, 2654435761, 805459861}
            const unsigned hx0 = (unsigned)x0;
            const unsigned hx1 = hx0 + 1u;
            const unsigned hy0 = (unsigned)y0 * 2654435761u;
            const unsigned hy1 = hy0 + 2654435761u;
            const unsigned hz0 = (unsigned)z0 * 805459861u;
            const unsigned hz1 = hz0 + 805459861u;

            // factored yz weights (shared across x-pair of corners)
            const float w00 = uy * uz, w01 = uy * wz, w10 = wy * uz, w11 = wy * wz;

            #define HG_CORNER(HX, HY, HZ, WX, WYZ)                         \
            {                                                              \
                const unsigned idx = ((HX) ^ (HY) ^ (HZ)) % S;             \
                const float4 f = scb[O + (int)idx];                        \
                const float w = (WX) * (WYZ);                              \
                a0 = fmaf(w, f.x, a0);                                     \
                a1 = fmaf(w, f.y, a1);                                     \
                a2 = fmaf(w, f.z, a2);                                     \
            }
            // corner order (i=x, j=y, k=z) matches OFFSETS enumeration
            HG_CORNER(hx0, hy0, hz0, ux, w00)
            HG_CORNER(hx0, hy0, hz1, ux, w01)
            HG_CORNER(hx0, hy1, hz0, ux, w10)
            HG_CORNER(hx0, hy1, hz1, ux, w11)
            HG_CORNER(hx1, hy0, hz0, wx, w00)
            HG_CORNER(hx1, hy0, hz1, wx, w01)
            HG_CORNER(hx1, hy1, hz0, wx, w10)
            HG_CORNER(hx1, hy1, hz1, wx, w11)
            #undef HG_CORNER
        }

        out[3 * i + 0] = a0;
        out[3 * i + 1] = a1;
        out[3 * i + 2] = a2;
    }
}

extern "C" void kernel_launch(void* const* d_in, const int* in_sizes, int n_in,
                              void* d_out, int out_size)
{
    const float* pts = (const float*)d_in[0];
    const int n = in_sizes[0] / 3;

    Params prm;
    for (int l = 0; l < NLOD; l++) prm.cb[l] = (const float*)d_in[1 + l];

    // Replicate the reference's LOD formula exactly in double precision:
    //   b = exp((log(64) - log(6)) / 9);  lod9 = int(1 + floor(6 * b**9))
    // 6*b^9 sits within fp noise of exactly 64.0, so the floor is decided by
    // libm rounding; compute it the same way numpy does and dispatch.
    const double b = exp((log(64.0) - log(6.0)) / 9.0);
    const double v9 = 6.0 * pow(b, 9.0);
    const int last_res = (int)(1.0 + floor(v9));

    int sm_count = 0;
    cudaDeviceGetAttribute(&sm_count, cudaDevAttrMultiProcessorCount, 0);
    if (sm_count <= 0) sm_count = 148;
    const int blocks = sm_count * 2;  // 2 CTAs/SM (84KB smem each)

    float* out = (float*)d_out;

    if (last_res == 65) {
        cudaFuncSetAttribute(hashgrid_kernel<65>,
                             cudaFuncAttributeMaxDynamicSharedMemorySize, SMEM_BYTES);
        hashgrid_kernel<65><<<blocks, THREADS, SMEM_BYTES>>>(pts, prm, out, n);
    } else {
        cudaFuncSetAttribute(hashgrid_kernel<64>,
                             cudaFuncAttributeMaxDynamicSharedMemorySize, SMEM_BYTES);
        hashgrid_kernel<64><<<blocks, THREADS, SMEM_BYTES>>>(pts, prm, out, n);
    }
}

// round 3
// speedup vs baseline: 1.8119x; 1.8119x over previous
#include <cuda_runtime.h>
#include <cuda_fp16.h>
#include <math.h>

// HashGrid: 10-level Instant-NGP hash encoding, 2M points, FEAT_DIM=3.
// R2: codebooks stored in smem as 4x fp16 (8 B/entry, LDS.64 gathers) to halve
// the saturated shared-crossbar traffic (ncu R1: L1 pipe 94.2%). Accumulation
// stays fp32; only feature representation is fp16 (~1e-4 rel err).

#define NLOD 10

struct Params { const float* cb[NLOD]; };

// sizes = min(lod^2, 1024) for lods {7,8,11,14,18,23,30,38,50,64/65}
__host__ __device__ constexpr int H_SIZES(int l) {
    constexpr int s[NLOD] = {49, 64, 121, 196, 324, 529, 900, 1024, 1024, 1024};
    return s[l];
}
__host__ __device__ constexpr int H_OFFS(int l) {
    constexpr int o[NLOD] = {0, 49, 113, 234, 430, 754, 1283, 2183, 3207, 4231};
    return o[l];
}
constexpr int H_TOTAL = 5255;
constexpr int SMEM_BYTES = H_TOTAL * 8;   // 42,040 bytes (uint2 per entry)
constexpr int THREADS = 512;

template <int LAST_RES>
__global__ __launch_bounds__(THREADS, 2)
void hashgrid_kernel(const float* __restrict__ pts, Params prm,
                     float* __restrict__ out, int n)
{
    extern __shared__ uint2 scb[];   // each entry: {half2(f0,f1), half2(f2,0)}

    // ---- Stage all codebooks into shared memory as packed fp16 ----
    #pragma unroll
    for (int l = 0; l < NLOD; l++) {
        const float* __restrict__ src = prm.cb[l];
        const int sz = H_SIZES(l);
        const int off = H_OFFS(l);
        for (int i = threadIdx.x; i < sz; i += THREADS) {
            __half2 h01 = __floats2half2_rn(src[3 * i + 0], src[3 * i + 1]);
            __half2 h23 = __floats2half2_rn(src[3 * i + 2], 0.0f);
            uint2 v;
            v.x = *reinterpret_cast<unsigned*>(&h01);
            v.y = *reinterpret_cast<unsigned*>(&h23);
            scb[off + i] = v;
        }
    }
    __syncthreads();

    const int stride = gridDim.x * THREADS;
    for (int i = blockIdx.x * THREADS + threadIdx.x; i < n; i += stride) {
        const float px = pts[3 * i + 0];
        const float py = pts[3 * i + 1];
        const float pz = pts[3 * i + 2];
        float a0 = 0.0f, a1 = 0.0f, a2 = 0.0f;

        #pragma unroll
        for (int l = 0; l < NLOD; l++) {
            constexpr int RESA[NLOD] = {7, 8, 11, 14, 18, 23, 30, 38, 50, LAST_RES};
            const int R = RESA[l];
            const unsigned S = (unsigned)H_SIZES(l);   // compile-time -> magic-number mod
            const int O = H_OFFS(l);
            const float scale = (float)(R - 1);

            const float xs = px * scale, ys = py * scale, zs = pz * scale;
            int x0 = (int)xs; x0 = x0 > R - 2 ? R - 2 : x0;  // xs >= 0 so trunc == floor
            int y0 = (int)ys; y0 = y0 > R - 2 ? R - 2 : y0;
            int z0 = (int)zs; z0 = z0 > R - 2 ? R - 2 : z0;
            const float wx = xs - (float)x0, wy = ys - (float)y0, wz = zs - (float)z0;
            const float ux = 1.0f - wx, uy = 1.0f - wy, uz = 1.0f - wz;

            // Instant-NGP primes: {1, 2654435761, 805459861}
            const unsigned hx0 = (unsigned)x0;
            const unsigned hx1 = hx0 + 1u;
            const unsigned hy0 = (unsigned)y0 * 2654435761u;
            const unsigned hy1 = hy0 + 2654435761u;
            const unsigned hz0 = (unsigned)z0 * 805459861u;
            const unsigned hz1 = hz0 + 805459861u;

            // factored yz weights (shared across x-pair of corners)
            const float w00 = uy * uz, w01 = uy * wz, w10 = wy * uz, w11 = wy * wz;

            #define HG_CORNER(HX, HY, HZ, WX, WYZ)                         \
            {                                                              \
                const unsigned idx = ((HX) ^ (HY) ^ (HZ)) % S;             \
                const uint2 v = scb[O + (int)idx];                         \
                const __half2 h01 = *reinterpret_cast<const __half2*>(&v.x); \
                const __half  h2  = *reinterpret_cast<const __half*>(&v.y);  \
                const float2 f01 = __half22float2(h01);                    \
                const float  f2  = __half2float(h2);                       \
                const float w = (WX) * (WYZ);                              \
                a0 = fmaf(w, f01.x, a0);                                   \
                a1 = fmaf(w, f01.y, a1);                                   \
                a2 = fmaf(w, f2,    a2);                                   \
            }
            // corner order (i=x, j=y, k=z) matches OFFSETS enumeration
            HG_CORNER(hx0, hy0, hz0, ux, w00)
            HG_CORNER(hx0, hy0, hz1, ux, w01)
            HG_CORNER(hx0, hy1, hz0, ux, w10)
            HG_CORNER(hx0, hy1, hz1, ux, w11)
            HG_CORNER(hx1, hy0, hz0, wx, w00)
            HG_CORNER(hx1, hy0, hz1, wx, w01)
            HG_CORNER(hx1, hy1, hz0, wx, w10)
            HG_CORNER(hx1, hy1, hz1, wx, w11)
            #undef HG_CORNER
        }

        out[3 * i + 0] = a0;
        out[3 * i + 1] = a1;
        out[3 * i + 2] = a2;
    }
}

extern "C" void kernel_launch(void* const* d_in, const int* in_sizes, int n_in,
                              void* d_out, int out_size)
{
    const float* pts = (const float*)d_in[0];
    const int n = in_sizes[0] / 3;

    Params prm;
    for (int l = 0; l < NLOD; l++) prm.cb[l] = (const float*)d_in[1 + l];

    // Replicate the reference's LOD formula exactly in double precision:
    //   b = exp((log(64) - log(6)) / 9);  lod9 = int(1 + floor(6 * b**9))
    // 6*b^9 sits within fp noise of exactly 64.0, so the floor is decided by
    // libm rounding; compute it the same way numpy does and dispatch.
    const double b = exp((log(64.0) - log(6.0)) / 9.0);
    const double v9 = 6.0 * pow(b, 9.0);
    const int last_res = (int)(1.0 + floor(v9));

    int sm_count = 0;
    cudaDeviceGetAttribute(&sm_count, cudaDevAttrMultiProcessorCount, 0);
    if (sm_count <= 0) sm_count = 148;
    const int blocks = sm_count * 2;  // 2 CTAs/SM

    float* out = (float*)d_out;

    if (last_res == 65) {
        cudaFuncSetAttribute(hashgrid_kernel<65>,
                             cudaFuncAttributeMaxDynamicSharedMemorySize, SMEM_BYTES);
        hashgrid_kernel<65><<<blocks, THREADS, SMEM_BYTES>>>(pts, prm, out, n);
    } else {
        cudaFuncSetAttribute(hashgrid_kernel<64>,
                             cudaFuncAttributeMaxDynamicSharedMemorySize, SMEM_BYTES);
        hashgrid_kernel<64><<<blocks, THREADS, SMEM_BYTES>>>(pts, prm, out, n);
    }
}